// round 4
// baseline (speedup 1.0000x reference)
#include <cuda_runtime.h>
#include <cstdint>

#define B_DIM 16
#define P_DIM 4096
#define T_DIM 1024
#define PCHUNK 512
#define NT 512
#define TPT 2                                  // 512 threads * 2 targets = 1024
#define NBLOCKS (B_DIM * (P_DIM / PCHUNK))     // 128

// Zero-initialized scratch; the finalize path restores everything to zero each
// call, so graph replays start clean with no init kernel.
__device__ unsigned long long g_best[B_DIM * T_DIM];  // holds ~key, 0 = empty
__device__ unsigned int g_done;

// ---- packed f32x2 helpers (sm_103a) ----
__device__ __forceinline__ unsigned long long pk2(float lo, float hi) {
    unsigned long long r;
    asm("mov.b64 %0, {%1, %2};" : "=l"(r) : "f"(lo), "f"(hi));
    return r;
}
__device__ __forceinline__ void upk2(unsigned long long v, float& lo, float& hi) {
    asm("mov.b64 {%0, %1}, %2;" : "=f"(lo), "=f"(hi) : "l"(v));
}
__device__ __forceinline__ unsigned long long add2(unsigned long long a, unsigned long long b) {
    unsigned long long r;
    asm("add.rn.f32x2 %0, %1, %2;" : "=l"(r) : "l"(a), "l"(b));
    return r;
}
__device__ __forceinline__ unsigned long long mul2(unsigned long long a, unsigned long long b) {
    unsigned long long r;
    asm("mul.rn.f32x2 %0, %1, %2;" : "=l"(r) : "l"(a), "l"(b));
    return r;
}
__device__ __forceinline__ unsigned long long fma2(unsigned long long a, unsigned long long b,
                                                   unsigned long long c) {
    unsigned long long r;
    asm("fma.rn.f32x2 %0, %1, %2, %3;" : "=l"(r) : "l"(a), "l"(b), "l"(c));
    return r;
}

__global__ void __launch_bounds__(NT, 1)
score_kernel(const float* __restrict__ pred, const float* __restrict__ gt,
             float* __restrict__ out) {
    const int b  = blockIdx.x;
    const int p0 = blockIdx.y * PCHUNK;

    __shared__ float s_x[PCHUNK];   // x + 128*cls  (class folded into coordinate)
    __shared__ float s_y[PCHUNK];

    {   // stage 512 preds, one per thread (SoA for packed LDS.128 later)
        const float* e = pred + ((size_t)b * P_DIM + p0 + threadIdx.x) * 3;
        float c = e[0];
        s_x[threadIdx.x] = fmaf(c, 128.0f, e[1]);
        s_y[threadIdx.x] = e[2];
    }
    __syncthreads();

    // per-thread targets: negated+class-folded coords, duplicated into f32x2
    unsigned long long ntx[TPT], nty[TPT];
    int best[TPT];
#pragma unroll
    for (int k = 0; k < TPT; k++) {
        const float* e = gt + ((size_t)b * T_DIM + threadIdx.x + k * NT) * 3;
        float c = e[0];
        float tx = -fmaf(c, 128.0f, e[1]);
        float ty = -e[2];
        ntx[k] = pk2(tx, tx);
        nty[k] = pk2(ty, ty);
        best[k] = 0x7F800000;   // +inf bits; positive floats order as ints
    }

    const float4* x4 = (const float4*)s_x;
    const float4* y4 = (const float4*)s_y;
#pragma unroll 2
    for (int j = 0; j < PCHUNK / 4; j++) {
        float4 qx = x4[j];                       // broadcast LDS.128
        float4 qy = y4[j];
        unsigned long long xa = pk2(qx.x, qx.y), xb = pk2(qx.z, qx.w);
        unsigned long long ya = pk2(qy.x, qy.y), yb = pk2(qy.z, qy.w);
        const int j0 = 4 * j;
#pragma unroll
        for (int k = 0; k < TPT; k++) {
            unsigned long long dxa = add2(xa, ntx[k]);
            unsigned long long dxb = add2(xb, ntx[k]);
            unsigned long long dya = add2(ya, nty[k]);
            unsigned long long dyb = add2(yb, nty[k]);
            unsigned long long sqa = mul2(dya, dya);
            unsigned long long sqb = mul2(dyb, dyb);
            unsigned long long d2a = fma2(dxa, dxa, sqa);
            unsigned long long d2b = fma2(dxb, dxb, sqb);
            float f0, f1, f2, f3;
            upk2(d2a, f0, f1);
            upk2(d2b, f2, f3);
            best[k] = min(best[k], (__float_as_int(f0) & 0xFFFFFE00) | (j0 + 0));
            best[k] = min(best[k], (__float_as_int(f1) & 0xFFFFFE00) | (j0 + 1));
            best[k] = min(best[k], (__float_as_int(f2) & 0xFFFFFE00) | (j0 + 2));
            best[k] = min(best[k], (__float_as_int(f3) & 0xFFFFFE00) | (j0 + 3));
        }
    }

#pragma unroll
    for (int k = 0; k < TPT; k++) {
        int d2part = best[k] & 0xFFFFFE00;
        if (d2part <= 0x41C80000) {              // d2 <= 25.0f (class folded in)
            unsigned p = (unsigned)(p0 + (best[k] & 511));
            unsigned long long key =
                ((unsigned long long)(unsigned)d2part << 32) | p;
            atomicMax(&g_best[b * T_DIM + threadIdx.x + k * NT], ~key);
        }
    }

    // ---- grid ticket: last block to finish does the finalize ----
    __threadfence();
    __syncthreads();
    __shared__ int s_last;
    if (threadIdx.x == 0)
        s_last = (atomicAdd(&g_done, 1u) == NBLOCKS - 1);
    __syncthreads();
    if (!s_last) return;
    __threadfence();   // acquire: make all blocks' g_best atomics visible

    // dedup best-preds per batch in smem bitmask, count distinct, compute f1
    __shared__ unsigned s_mask[B_DIM * (P_DIM / 32)];   // 2048 words = 8KB
    for (int i = threadIdx.x; i < B_DIM * (P_DIM / 32); i += NT) s_mask[i] = 0u;
    __syncthreads();

    int cnt = 0;
    for (int i = threadIdx.x; i < B_DIM * T_DIM; i += NT) {
        unsigned long long v = g_best[i];
        if (v != 0ull) {
            g_best[i] = 0ull;                    // restore for next replay
            unsigned p  = (unsigned)(~v) & (P_DIM - 1);
            int bb      = i >> 10;               // i / T_DIM
            unsigned bit = 1u << (p & 31u);
            unsigned old = atomicOr(&s_mask[bb * (P_DIM / 32) + (p >> 5)], bit);
            cnt += (old & bit) ? 0 : 1;
        }
    }

#pragma unroll
    for (int o = 16; o; o >>= 1) cnt += __shfl_down_sync(0xFFFFFFFFu, cnt, o);
    __shared__ int wsum[NT / 32];
    if ((threadIdx.x & 31) == 0) wsum[threadIdx.x >> 5] = cnt;
    __syncthreads();
    if (threadIdx.x == 0) {
        int s = 0;
#pragma unroll
        for (int w = 0; w < NT / 32; w++) s += wsum[w];
        float tp = (float)s;
        float fp = (float)(B_DIM * P_DIM) - tp;
        float fn = (float)(B_DIM * T_DIM) - tp;
        const float eps = 1e-6f;
        float precision = (tp + eps) / (tp + eps + fp + eps);
        float recall    = (tp + eps) / (tp + fn + eps);
        float f1 = 2.0f * precision * recall / (precision + recall);
        out[0] = 1.0f - f1;
        g_done = 0u;                             // restore for next replay
    }
}

extern "C" void kernel_launch(void* const* d_in, const int* in_sizes, int n_in,
                              void* d_out, int out_size) {
    const float* pred = (const float*)d_in[0];
    const float* gt   = (const float*)d_in[1];
    if (n_in >= 2 && in_sizes[0] == B_DIM * T_DIM * 3) {   // swapped-order guard
        pred = (const float*)d_in[1];
        gt   = (const float*)d_in[0];
    }
    float* out = (float*)d_out;

    dim3 grid(B_DIM, P_DIM / PCHUNK);   // 16 x 8 = 128 blocks, single wave
    score_kernel<<<grid, NT>>>(pred, gt, out);
}

// round 5
// speedup vs baseline: 1.6224x; 1.6224x over previous
#include <cuda_runtime.h>
#include <cstdint>

#define B_DIM 16
#define P_DIM 4096
#define T_DIM 1024
#define NTH   512
#define HALVES 2
#define NBLOCKS (B_DIM * HALVES)      // 32
#define NBINS 256                     // 4 classes * 8x8 cells
#define PPT (P_DIM / NTH)             // 8 preds per thread

// Zero-initialized scratch; last block restores everything to zero each call,
// so CUDA-graph replays start clean (no init kernel).
__device__ unsigned g_mask[B_DIM * (P_DIM / 32)];   // per-batch hit bitmask
__device__ unsigned g_tp;
__device__ unsigned g_done;

__global__ void __launch_bounds__(NTH, 1)
loss_kernel(const float* __restrict__ pred, const float* __restrict__ gt,
            float* __restrict__ out)
{
    const int b    = blockIdx.x;
    const int half = blockIdx.y;
    const int tid  = threadIdx.x;

    __shared__ float2         s_xy[P_DIM];     // binned pred coords (32KB)
    __shared__ unsigned short s_pid[P_DIM];    // slot -> original pred id (8KB)
    __shared__ unsigned s_hist[NBINS];
    __shared__ unsigned s_scan[NBINS];         // inclusive scan (bin end)
    __shared__ unsigned s_cur[NBINS];
    __shared__ int s_last;

    if (tid < NBINS) s_hist[tid] = 0u;
    __syncthreads();

    // ---- phase 1: histogram preds into (class, cell) bins ----
    float px[PPT], py[PPT];
    int   pbin[PPT];
#pragma unroll
    for (int i = 0; i < PPT; i++) {
        const int p = tid + i * NTH;                      // coalesced
        const float* e = pred + ((size_t)b * P_DIM + p) * 3;
        float c = e[0], x = e[1], y = e[2];
        int cx = min(7, (int)(x * 0.125f));
        int cy = min(7, (int)(y * 0.125f));
        pbin[i] = (int)c * 64 + cy * 8 + cx;
        px[i] = x; py[i] = y;
        atomicAdd(&s_hist[pbin[i]], 1u);
    }
    __syncthreads();

    // ---- inclusive scan over 256 bins (Hillis-Steele) ----
    if (tid < NBINS) s_scan[tid] = s_hist[tid];
    __syncthreads();
    for (int off = 1; off < NBINS; off <<= 1) {
        unsigned v = 0;
        if (tid < NBINS) {
            v = s_scan[tid];
            if (tid >= off) v += s_scan[tid - off];
        }
        __syncthreads();
        if (tid < NBINS) s_scan[tid] = v;
        __syncthreads();
    }
    if (tid < NBINS) s_cur[tid] = s_scan[tid] - s_hist[tid];  // exclusive start
    __syncthreads();

    // ---- phase 2: scatter preds into bins ----
#pragma unroll
    for (int i = 0; i < PPT; i++) {
        unsigned pos = atomicAdd(&s_cur[pbin[i]], 1u);
        s_xy[pos]  = make_float2(px[i], py[i]);
        s_pid[pos] = (unsigned short)(tid + i * NTH);
    }
    __syncthreads();

    // ---- phase 3: each thread handles one target ----
    const int t = half * NTH + tid;
    const float* e = gt + ((size_t)b * T_DIM + t) * 3;
    const float tc = e[0], tx = e[1], ty = e[2];
    const int tcls = (int)tc;
    const int cx0 = max(0, (int)((tx - 5.0f) * 0.125f));
    const int cx1 = min(7, (int)((tx + 5.0f) * 0.125f));
    const int cy0 = max(0, (int)((ty - 5.0f) * 0.125f));
    const int cy1 = min(7, (int)((ty + 5.0f) * 0.125f));

    float bestd2 = __int_as_float(0x7f800000);  // +inf
    int   bestslot = 0;
    for (int cy = cy0; cy <= cy1; cy++) {
        for (int cx = cx0; cx <= cx1; cx++) {
            const int bin = tcls * 64 + cy * 8 + cx;
            const unsigned end = s_scan[bin];
            for (unsigned s = end - s_hist[bin]; s < end; s++) {
                float2 q = s_xy[s];
                float dx = q.x - tx;
                float dy = q.y - ty;
                float d2 = fmaf(dx, dx, dy * dy);
                if (d2 < bestd2) { bestd2 = d2; bestslot = (int)s; }
            }
        }
    }

    // ---- dedup + count (order-independent => deterministic) ----
    int newbit = 0;
    if (bestd2 <= 25.0f) {
        unsigned p   = s_pid[bestslot];
        unsigned bit = 1u << (p & 31u);
        unsigned old = atomicOr(&g_mask[b * (P_DIM / 32) + (p >> 5)], bit);
        newbit = (old & bit) ? 0 : 1;
    }
    int cnt = __syncthreads_count(newbit);

    if (tid == 0) {
        if (cnt) atomicAdd(&g_tp, (unsigned)cnt);
        __threadfence();
        s_last = (atomicAdd(&g_done, 1u) == NBLOCKS - 1);
    }
    __syncthreads();
    if (!s_last) return;

    // ---- last block: compute f1, reset scratch for next replay ----
    __threadfence();
    for (int i = tid; i < B_DIM * (P_DIM / 32); i += NTH) g_mask[i] = 0u;
    if (tid == 0) {
        float tp = (float)atomicAdd(&g_tp, 0u);
        float fp = (float)(B_DIM * P_DIM) - tp;
        float fn = (float)(B_DIM * T_DIM) - tp;
        const float eps = 1e-6f;
        float precision = (tp + eps) / (tp + eps + fp + eps);
        float recall    = (tp + eps) / (tp + fn + eps);
        float f1 = 2.0f * precision * recall / (precision + recall);
        out[0] = 1.0f - f1;
        g_tp = 0u;
        g_done = 0u;
    }
}

extern "C" void kernel_launch(void* const* d_in, const int* in_sizes, int n_in,
                              void* d_out, int out_size) {
    const float* pred = (const float*)d_in[0];
    const float* gt   = (const float*)d_in[1];
    if (n_in >= 2 && in_sizes[0] == B_DIM * T_DIM * 3) {   // swapped-order guard
        pred = (const float*)d_in[1];
        gt   = (const float*)d_in[0];
    }
    float* out = (float*)d_out;

    dim3 grid(B_DIM, HALVES);   // 32 blocks
    loss_kernel<<<grid, NTH>>>(pred, gt, out);
}